// round 1
// baseline (speedup 1.0000x reference)
#include <cuda_runtime.h>

// Problem shape (fixed by setup_inputs): B=8, H=512, W=512, C=16, fp32.
// out[b,y,x,c] = bilinear(image[b], y - flow[b,y,x,0], x - flow[b,y,x,1])
// with tfa clamping: floor clamped to [0, size-2], alpha clamped to [0,1].

#define BB 8
#define HH 512
#define WW 512
#define CC 16

// One pixel is handled by 4 consecutive threads; each thread does one float4
// channel chunk (16 B). A warp covers 8 consecutive pixels -> each of the 4
// bilinear gather loads is ~512B-contiguous across the warp.
__global__ __launch_bounds__(256, 8)
void warp_bilinear_kernel(const float* __restrict__ image,
                          const float* __restrict__ flow,
                          float* __restrict__ out)
{
    unsigned tid   = blockIdx.x * 256u + threadIdx.x;
    unsigned chunk = tid & 3u;          // which float4 of the 16-channel vector
    unsigned p     = tid >> 2;          // global pixel index in [0, B*H*W)

    unsigned x = p & (WW - 1u);         // W = 512
    unsigned y = (p >> 9) & (HH - 1u);  // H = 512
    unsigned b = p >> 18;               // B = 8

    // flow[..,0] = dy, flow[..,1] = dx  (contiguous float2 per pixel)
    float2 f = __ldg(reinterpret_cast<const float2*>(flow) + p);
    float qy = (float)y - f.x;
    float qx = (float)x - f.y;

    float fy = fminf(fmaxf(floorf(qy), 0.0f), (float)(HH - 2));
    float fx = fminf(fmaxf(floorf(qx), 0.0f), (float)(WW - 2));
    float ay = fminf(fmaxf(qy - fy, 0.0f), 1.0f);
    float ax = fminf(fmaxf(qx - fx, 0.0f), 1.0f);
    int iy = (int)fy;
    int ix = (int)fx;

    // float4-granular addressing: C/4 = 4 chunks per pixel.
    const float4* __restrict__ img4 = reinterpret_cast<const float4*>(image);
    size_t base = ((size_t)(((b * HH + (unsigned)iy) * WW) + (unsigned)ix)) * (CC / 4) + chunk;
    const size_t dC = CC / 4;            // next pixel in x
    const size_t dW = (size_t)WW * (CC / 4); // next row

    float4 tl = __ldg(img4 + base);
    float4 tr = __ldg(img4 + base + dC);
    float4 bl = __ldg(img4 + base + dW);
    float4 br = __ldg(img4 + base + dW + dC);

    float4 top, bot, o;
    top.x = fmaf(ax, tr.x - tl.x, tl.x);
    top.y = fmaf(ax, tr.y - tl.y, tl.y);
    top.z = fmaf(ax, tr.z - tl.z, tl.z);
    top.w = fmaf(ax, tr.w - tl.w, tl.w);
    bot.x = fmaf(ax, br.x - bl.x, bl.x);
    bot.y = fmaf(ax, br.y - bl.y, bl.y);
    bot.z = fmaf(ax, br.z - bl.z, bl.z);
    bot.w = fmaf(ax, br.w - bl.w, bl.w);
    o.x = fmaf(ay, bot.x - top.x, top.x);
    o.y = fmaf(ay, bot.y - top.y, top.y);
    o.z = fmaf(ay, bot.z - top.z, top.z);
    o.w = fmaf(ay, bot.w - top.w, top.w);

    reinterpret_cast<float4*>(out)[(size_t)p * (CC / 4) + chunk] = o;
}

extern "C" void kernel_launch(void* const* d_in, const int* in_sizes, int n_in,
                              void* d_out, int out_size)
{
    const float* image = (const float*)d_in[0];
    const float* flow  = (const float*)d_in[1];
    float* out = (float*)d_out;

    // Total threads = B*H*W*4 = 8,388,608 -> exactly 32768 blocks of 256.
    const unsigned total_threads = BB * HH * WW * 4u;
    const unsigned blocks = total_threads / 256u;
    warp_bilinear_kernel<<<blocks, 256>>>(image, flow, out);
}